// round 1
// baseline (speedup 1.0000x reference)
#include <cuda_runtime.h>
#include <math.h>

#define G 1024
#define NNODE 256
#define FIN 128
#define DH 256

// ---------------- scratch (device globals; no allocations allowed) -------------
__device__ float g_norm0[G * NNODE];
__device__ float g_H  [G * NNODE * DH];   // layer0: (x*norm)@W0
__device__ float g_X1 [G * NNODE * DH];   // layer0 conv output
__device__ float g_Xp1[G * 32 * DH];
__device__ float g_A1 [G * 32 * 32];
__device__ float g_norm1[G * 32];
__device__ float g_H1 [G * 32 * DH];
__device__ float g_X2 [G * 32 * DH];
__device__ float g_Xp2[G * 16 * DH];
__device__ float g_A2 [G * 16 * 16];
__device__ float g_norm2[G * 16];
__device__ float g_H2 [G * 16 * DH];
__device__ float g_X3 [G * 16 * DH];
__device__ float g_Xp3[G * 8 * DH];
__device__ float g_read[G * 1536];
__device__ float g_h  [G * 128];

// ---------------- degree -> norm for the initial adjacency ---------------------
__global__ void degnorm_kernel(const float* __restrict__ adj, float* __restrict__ nrm)
{
    int row = blockIdx.x * 8 + (threadIdx.x >> 5);
    int lane = threadIdx.x & 31;
    const float* a = adj + (long)row * 256;
    float s = 0.f;
#pragma unroll
    for (int q = 0; q < 8; q++) s += a[lane + 32 * q];
#pragma unroll
    for (int sh = 16; sh > 0; sh >>= 1) s += __shfl_down_sync(0xffffffffu, s, sh);
    if (lane == 0) nrm[row] = rsqrtf(fmaxf(s, 1.f));
}

// ---------------- generic tiled SGEMM with fused epilogues ---------------------
// C[g] = epilogue( (rowscaleA .* A[g]) @ B[g] )
// epilogue: optionally *rsC[row], +bias[col], leaky_relu(0.01)
#define BM 128
#define BN 128
#define BK 8

__global__ void sgemm_kernel(const float* __restrict__ A, const float* __restrict__ B,
                             float* __restrict__ C,
                             int M, int N, int K,
                             long bA, long bB, long bC,
                             const float* __restrict__ rsA, int rsAstride,
                             const float* __restrict__ rsC, int rsCstride,
                             const float* __restrict__ bias, int leaky)
{
    int g = blockIdx.z;
    const float* Ag = A + (long)g * bA;
    const float* Bg = B + (long)g * bB;
    float* Cg = C + (long)g * bC;
    const float* rsAg = rsA ? rsA + (long)g * rsAstride : nullptr;
    const float* rsCg = rsC ? rsC + (long)g * rsCstride : nullptr;

    int bm = blockIdx.y * BM;
    int bn = blockIdx.x * BN;

    __shared__ __align__(16) float sA[BK][BM + 4];
    __shared__ __align__(16) float sB[BK][BN + 4];

    int tid = threadIdx.x;                 // 256 threads
    int a_row = tid >> 1;                  // 0..127
    int a_col = (tid & 1) * 4;             // 0 or 4
    int b_row = tid >> 5;                  // 0..7
    int b_col = (tid & 31) * 4;            // 0..124
    int tr = tid >> 4;                     // 0..15
    int tc = tid & 15;                     // 0..15

    float acc[8][8];
#pragma unroll
    for (int i = 0; i < 8; i++)
#pragma unroll
        for (int j = 0; j < 8; j++) acc[i][j] = 0.f;

    float aScale = rsAg ? rsAg[bm + a_row] : 1.f;

    for (int k0 = 0; k0 < K; k0 += BK) {
        float4 av = *(const float4*)(Ag + (long)(bm + a_row) * K + k0 + a_col);
        av.x *= aScale; av.y *= aScale; av.z *= aScale; av.w *= aScale;
        sA[a_col + 0][a_row] = av.x;
        sA[a_col + 1][a_row] = av.y;
        sA[a_col + 2][a_row] = av.z;
        sA[a_col + 3][a_row] = av.w;
        float4 bv = *(const float4*)(Bg + (long)(k0 + b_row) * N + bn + b_col);
        *(float4*)&sB[b_row][b_col] = bv;
        __syncthreads();
#pragma unroll
        for (int k = 0; k < BK; k++) {
            float4 a0 = *(const float4*)&sA[k][tr * 4];
            float4 a1 = *(const float4*)&sA[k][tr * 4 + 64];
            float4 b0 = *(const float4*)&sB[k][tc * 4];
            float4 b1 = *(const float4*)&sB[k][tc * 4 + 64];
            float ar[8] = {a0.x, a0.y, a0.z, a0.w, a1.x, a1.y, a1.z, a1.w};
            float br[8] = {b0.x, b0.y, b0.z, b0.w, b1.x, b1.y, b1.z, b1.w};
#pragma unroll
            for (int i = 0; i < 8; i++)
#pragma unroll
                for (int j = 0; j < 8; j++) acc[i][j] += ar[i] * br[j];
        }
        __syncthreads();
    }

#pragma unroll
    for (int i = 0; i < 8; i++) {
        int row = bm + ((i < 4) ? (tr * 4 + i) : (64 + tr * 4 + i - 4));
        float rs = rsCg ? rsCg[row - bm + (bm % 0x7fffffff) * 0] : 1.f; // placeholder
        rs = rsCg ? rsCg[row] : 1.f;
#pragma unroll
        for (int jg = 0; jg < 2; jg++) {
            int col = bn + tc * 4 + jg * 64;
            float v[4];
#pragma unroll
            for (int jj = 0; jj < 4; jj++) {
                float c = acc[i][jg * 4 + jj] * rs;
                if (bias) c += bias[col + jj];
                if (leaky) c = (c > 0.f) ? c : 0.01f * c;
                v[jj] = c;
            }
            float4 o = make_float4(v[0], v[1], v[2], v[3]);
            *(float4*)(Cg + (long)row * N + col) = o;
        }
    }
}

// ---------------- small batched conv: X = leaky(adj@H * norm + b) ---------------
template <int NN>
__global__ void conv_small_kernel(const float* __restrict__ A, const float* __restrict__ H,
                                  const float* __restrict__ nrm, const float* __restrict__ bias,
                                  float* __restrict__ X)
{
    int g = blockIdx.x;
    __shared__ float sAdj[NN][NN + 1];
    __shared__ float sH[NN][256];
    const float* Ag = A + (long)g * NN * NN;
    const float* Hg = H + (long)g * NN * 256;
    int tid = threadIdx.x; // 256
    for (int t = tid; t < NN * NN; t += 256) sAdj[t / NN][t % NN] = Ag[t];
    for (int t = tid; t < NN * 256; t += 256) sH[t / 256][t % 256] = Hg[t];
    __syncthreads();
    int j = tid;
    float bj = bias[j];
#pragma unroll 4
    for (int i = 0; i < NN; i++) {
        float acc = 0.f;
#pragma unroll
        for (int k = 0; k < NN; k++) acc += sAdj[i][k] * sH[k][j];
        float v = acc * nrm[(long)g * NN + i] + bj;
        X[(long)g * NN * 256 + (long)i * 256 + j] = (v > 0.f) ? v : 0.01f * v;
    }
}

// ---------------- SAGPool: score -> topk -> gather/gate -> readout -> subgraph --
template <int NV, int KK>
__global__ void pool_kernel(const float* __restrict__ X, const float* __restrict__ A,
                            const float* __restrict__ nrm,
                            const float* __restrict__ Ws, const float* __restrict__ bs,
                            float* __restrict__ Xp, float* __restrict__ Aout,
                            float* __restrict__ normOut, float* __restrict__ readout,
                            int roff)
{
    int g = blockIdx.x;
    const float* Xg = X + (long)g * NV * 256;
    const float* Ag = A + (long)g * NV * NV;
    const float* ng = nrm + (long)g * NV;

    __shared__ float sWs[256];
    __shared__ float spre[NV];
    __shared__ float ssc[NV];
    __shared__ int   sidx[NV];
    __shared__ float sAn[KK * KK];

    int tid = threadIdx.x, lane = tid & 31, warp = tid >> 5;
    sWs[tid] = Ws[tid];
    __syncthreads();

    // s_pre[r] = norm[r] * dot(x[r], Ws)
    for (int r = warp; r < NV; r += 8) {
        float acc = 0.f;
        for (int q = lane; q < 256; q += 32) acc += Xg[(long)r * 256 + q] * sWs[q];
#pragma unroll
        for (int s = 16; s > 0; s >>= 1) acc += __shfl_down_sync(0xffffffffu, acc, s);
        if (lane == 0) spre[r] = ng[r] * acc;
    }
    __syncthreads();

    // score[r] = norm[r] * dot(adj[r], s_pre) + bs
    float bsv = bs[0];
    for (int r = warp; r < NV; r += 8) {
        float acc = 0.f;
        for (int q = lane; q < NV; q += 32) acc += Ag[(long)r * NV + q] * spre[q];
#pragma unroll
        for (int s = 16; s > 0; s >>= 1) acc += __shfl_down_sync(0xffffffffu, acc, s);
        if (lane == 0) { ssc[r] = ng[r] * acc + bsv; sidx[r] = r; }
    }
    __syncthreads();

    // bitonic sort, descending by score, ties -> lower index first
    for (int ksz = 2; ksz <= NV; ksz <<= 1) {
        for (int j = ksz >> 1; j > 0; j >>= 1) {
            if (tid < NV) {
                int ixj = tid ^ j;
                if (ixj > tid) {
                    float s1 = ssc[tid], s2 = ssc[ixj];
                    int i1 = sidx[tid], i2 = sidx[ixj];
                    bool firstWorse = (s1 < s2) || (s1 == s2 && i1 > i2);
                    bool descRegion = ((tid & ksz) == 0);
                    bool doSwap = descRegion ? firstWorse : !firstWorse;
                    if (doSwap) {
                        ssc[tid] = s2; ssc[ixj] = s1;
                        sidx[tid] = i2; sidx[ixj] = i1;
                    }
                }
            }
            __syncthreads();
        }
    }

    // gates = tanh(topk scores)
    if (tid < KK) ssc[tid] = tanhf(ssc[tid]);
    __syncthreads();

    // gather + gate + sum/max readout (one column per thread)
    {
        int j = tid;
        float csum = 0.f, cmax = -3.402823466e38f;
#pragma unroll 4
        for (int r = 0; r < KK; r++) {
            int row = sidx[r];
            float v = Xg[(long)row * 256 + j] * ssc[r];
            Xp[(long)g * KK * 256 + (long)r * 256 + j] = v;
            csum += v;
            cmax = fmaxf(cmax, v);
        }
        readout[(long)g * 1536 + roff + j] = csum;
        readout[(long)g * 1536 + roff + 256 + j] = cmax;
    }

    // induced sub-adjacency + next-layer norm
    if (Aout) {
        for (int t = tid; t < KK * KK; t += 256) {
            int r = t / KK, c = t % KK;
            sAn[t] = Ag[(long)sidx[r] * NV + sidx[c]];
        }
        __syncthreads();
        for (int t = tid; t < KK * KK; t += 256) Aout[(long)g * KK * KK + t] = sAn[t];
        if (tid < KK) {
            float d = 0.f;
#pragma unroll
            for (int c = 0; c < KK; c++) d += sAn[tid * KK + c];
            normOut[(long)g * KK + tid] = rsqrtf(fmaxf(d, 1.f));
        }
    }
}

// ---------------- final head: out = sigmoid(h @ Wd2 + bd2) ----------------------
__global__ void head_kernel(const float* __restrict__ H, const float* __restrict__ Wd2,
                            const float* __restrict__ bd2, float* __restrict__ out)
{
    int g = blockIdx.x;
    int o = threadIdx.x >> 5;     // 0 or 1
    int lane = threadIdx.x & 31;
    float acc = 0.f;
#pragma unroll
    for (int k = lane; k < 128; k += 32) acc += H[(long)g * 128 + k] * Wd2[k * 2 + o];
#pragma unroll
    for (int s = 16; s > 0; s >>= 1) acc += __shfl_down_sync(0xffffffffu, acc, s);
    if (lane == 0) {
        float z = acc + bd2[o];
        out[g * 2 + o] = 1.f / (1.f + expf(-z));
    }
}

// --------------------------------- launch --------------------------------------
extern "C" void kernel_launch(void* const* d_in, const int* in_sizes, int n_in,
                              void* d_out, int out_size)
{
    const float* feat = (const float*)d_in[0];
    const float* adj  = (const float*)d_in[1];
    const float* W0   = (const float*)d_in[2];
    const float* b0   = (const float*)d_in[3];
    const float* Ws0  = (const float*)d_in[4];
    const float* bs0  = (const float*)d_in[5];
    const float* W1   = (const float*)d_in[6];
    const float* b1   = (const float*)d_in[7];
    const float* Ws1  = (const float*)d_in[8];
    const float* bs1  = (const float*)d_in[9];
    const float* W2   = (const float*)d_in[10];
    const float* b2   = (const float*)d_in[11];
    const float* Ws2  = (const float*)d_in[12];
    const float* bs2  = (const float*)d_in[13];
    const float* Wd1  = (const float*)d_in[14];
    const float* bd1  = (const float*)d_in[15];
    const float* Wd2  = (const float*)d_in[16];
    const float* bd2  = (const float*)d_in[17];
    float* out = (float*)d_out;

    float *p_norm0, *p_H, *p_X1, *p_Xp1, *p_A1, *p_norm1, *p_H1, *p_X2;
    float *p_Xp2, *p_A2, *p_norm2, *p_H2, *p_X3, *p_Xp3, *p_read, *p_h;
    cudaGetSymbolAddress((void**)&p_norm0, g_norm0);
    cudaGetSymbolAddress((void**)&p_H, g_H);
    cudaGetSymbolAddress((void**)&p_X1, g_X1);
    cudaGetSymbolAddress((void**)&p_Xp1, g_Xp1);
    cudaGetSymbolAddress((void**)&p_A1, g_A1);
    cudaGetSymbolAddress((void**)&p_norm1, g_norm1);
    cudaGetSymbolAddress((void**)&p_H1, g_H1);
    cudaGetSymbolAddress((void**)&p_X2, g_X2);
    cudaGetSymbolAddress((void**)&p_Xp2, g_Xp2);
    cudaGetSymbolAddress((void**)&p_A2, g_A2);
    cudaGetSymbolAddress((void**)&p_norm2, g_norm2);
    cudaGetSymbolAddress((void**)&p_H2, g_H2);
    cudaGetSymbolAddress((void**)&p_X3, g_X3);
    cudaGetSymbolAddress((void**)&p_Xp3, g_Xp3);
    cudaGetSymbolAddress((void**)&p_read, g_read);
    cudaGetSymbolAddress((void**)&p_h, g_h);

    // layer 0
    degnorm_kernel<<<G * NNODE / 8, 256>>>(adj, p_norm0);
    sgemm_kernel<<<dim3(2, 2048, 1), 256>>>(feat, W0, p_H, G * NNODE, DH, FIN,
                                            0, 0, 0, p_norm0, 0, nullptr, 0, nullptr, 0);
    sgemm_kernel<<<dim3(2, 2, 1024), 256>>>(adj, p_H, p_X1, NNODE, DH, NNODE,
                                            (long)NNODE * NNODE, (long)NNODE * DH, (long)NNODE * DH,
                                            nullptr, 0, p_norm0, NNODE, b0, 1);
    pool_kernel<256, 32><<<G, 256>>>(p_X1, adj, p_norm0, Ws0, bs0,
                                     p_Xp1, p_A1, p_norm1, p_read, 0);
    // layer 1
    sgemm_kernel<<<dim3(2, 256, 1), 256>>>(p_Xp1, W1, p_H1, G * 32, DH, DH,
                                           0, 0, 0, p_norm1, 0, nullptr, 0, nullptr, 0);
    conv_small_kernel<32><<<G, 256>>>(p_A1, p_H1, p_norm1, b1, p_X2);
    pool_kernel<32, 16><<<G, 256>>>(p_X2, p_A1, p_norm1, Ws1, bs1,
                                    p_Xp2, p_A2, p_norm2, p_read, 512);
    // layer 2
    sgemm_kernel<<<dim3(2, 128, 1), 256>>>(p_Xp2, W2, p_H2, G * 16, DH, DH,
                                           0, 0, 0, p_norm2, 0, nullptr, 0, nullptr, 0);
    conv_small_kernel<16><<<G, 256>>>(p_A2, p_H2, p_norm2, b2, p_X3);
    pool_kernel<16, 8><<<G, 256>>>(p_X3, p_A2, p_norm2, Ws2, bs2,
                                   p_Xp3, nullptr, nullptr, p_read, 1024);
    // MLP head
    sgemm_kernel<<<dim3(1, 8, 1), 256>>>(p_read, Wd1, p_h, G, 128, 1536,
                                         0, 0, 0, nullptr, 0, nullptr, 0, bd1, 1);
    head_kernel<<<G, 64>>>(p_h, Wd2, bd2, out);
}